// round 8
// baseline (speedup 1.0000x reference)
#include <cuda_runtime.h>
#include <cstdint>

// Swin shifted-window attention, fused, tf32 mma.sync, 2 CTAs/SM.
// Weights pre-rounded to tf32 in __device__ globals; B-fragments loaded
// directly via LDG (no smem staging, no staging barriers).
// A-fragments register-hoisted across weight chunks.
// out+proj folded into Wc = w_proj@w_out (pre-kernel).

#define SA   100
#define SV   104
#define SP   68

#define F_XW 0
#define F_K  6400
#define F_V  12800
#define F_P  19456
#define SMEM_FLOATS 23808
#define SMEM_BYTES  (SMEM_FLOATS * 4)

__device__ float g_wq[288 * 96];   // tf32-rounded w_qkv
__device__ float g_wc[96 * 96];    // tf32-rounded w_proj @ w_out
__device__ float g_bc[96];         // w_proj @ b_out + b_proj

static __device__ __forceinline__ float tf32r(float x) {
    float y; asm("cvt.rna.tf32.f32 %0, %1;" : "=f"(y) : "f"(x)); return y;
}
static __device__ __forceinline__ void mma8(float* d, float a0, float a1,
                                            float a2, float a3,
                                            float b0, float b1) {
    asm volatile(
        "mma.sync.aligned.m16n8k8.row.col.f32.tf32.tf32.f32 "
        "{%0,%1,%2,%3}, {%4,%5,%6,%7}, {%8,%9}, {%0,%1,%2,%3};"
        : "+f"(d[0]), "+f"(d[1]), "+f"(d[2]), "+f"(d[3])
        : "r"(__float_as_uint(a0)), "r"(__float_as_uint(a1)),
          "r"(__float_as_uint(a2)), "r"(__float_as_uint(a3)),
          "r"(__float_as_uint(b0)), "r"(__float_as_uint(b1)));
}

// ---- pre-kernels ----
__global__ void prep_wq(const float* __restrict__ w_qkv) {
    int i = blockIdx.x * 256 + threadIdx.x;
    if (i < 288 * 96) g_wq[i] = tf32r(w_qkv[i]);
}
__global__ void combine_wb(const float* __restrict__ w_out, const float* __restrict__ b_out,
                           const float* __restrict__ w_proj, const float* __restrict__ b_proj) {
    int row = blockIdx.x, col = threadIdx.x;
    float s = 0.f;
    #pragma unroll 4
    for (int k = 0; k < 96; k++) s += w_proj[row * 96 + k] * w_out[k * 96 + col];
    g_wc[row * 96 + col] = tf32r(s);
    if (col == 0) {
        float bs = b_proj[row];
        for (int k = 0; k < 96; k++) bs += w_proj[row * 96 + k] * b_out[k];
        g_bc[row] = bs;
    }
}

__global__ __launch_bounds__(256, 2)
void swin_mma3_kernel(const float* __restrict__ x,
                      const float* __restrict__ ln_g, const float* __restrict__ ln_b,
                      const float* __restrict__ b_qkv,
                      float* __restrict__ out)
{
    extern __shared__ float sm[];
    float* XW = sm + F_XW;   // x -> y -> Q -> final result
    float* Kb = sm + F_K;    // K -> O (per-head columns)
    float* Vb = sm + F_V;    // V
    float* Pb = sm + F_P;    // S -> P

    const int tid  = threadIdx.x;
    const int wid  = tid >> 5;
    const int lane = tid & 31;
    const int g    = lane >> 2;
    const int t4   = lane & 3;
    const int wm   = wid & 3;
    const int wn   = wid >> 2;

    const int wb = blockIdx.x;
    const int b  = wb >> 10;
    const int wy = (wb >> 5) & 31, wx = wb & 31;
    const int h0 = wy * 8, w0 = wx * 8;

    // ---- gather (roll folded) ----
    for (int li = tid; li < 64 * 96; li += 256) {
        int tk = li & 63, c = li >> 6;
        int hh = (h0 + (tk >> 3) + 4) & 255;
        int wc = (w0 + (tk & 7) + 4) & 255;
        XW[tk * SA + c] = x[((b * 96 + c) * 256 + hh) * 256 + wc];
    }
    __syncthreads();

    // ---- LayerNorm (4 lanes/token), write back tf32 ----
    {
        int tk = tid >> 2, s = tid & 3;
        float sum = 0.f, sq = 0.f;
        for (int c = s; c < 96; c += 4) {
            float v = XW[tk * SA + c];
            sum += v; sq += v * v;
        }
        sum += __shfl_xor_sync(0xffffffffu, sum, 1);
        sum += __shfl_xor_sync(0xffffffffu, sum, 2);
        sq  += __shfl_xor_sync(0xffffffffu, sq, 1);
        sq  += __shfl_xor_sync(0xffffffffu, sq, 2);
        float mu = sum * (1.f / 96.f);
        float rs = rsqrtf(sq * (1.f / 96.f) - mu * mu + 1e-5f);
        for (int c = s; c < 96; c += 4) {
            float v = XW[tk * SA + c];
            XW[tk * SA + c] = tf32r((v - mu) * rs * ln_g[c] + ln_b[c]);
        }
    }
    __syncthreads();

    const float qscale = 0.17677669529663687f;  // 1/sqrt(32)
    const int   r0 = wm * 16 + g;

    // ---- snapshot A-fragments of y (reused across all 9 QKV chunks) ----
    float af[12][4];
    #pragma unroll
    for (int kk = 0; kk < 12; kk++) {
        const float* Ar = XW + r0 * SA + kk * 8 + t4;
        af[kk][0] = Ar[0];
        af[kk][1] = Ar[8 * SA];
        af[kk][2] = Ar[4];
        af[kk][3] = Ar[8 * SA + 4];
    }
    __syncthreads();   // all warps hold frags before XW is overwritten by Q

    // ---- QKV: 9 chunks of 32 features, B-fragments via direct LDG ----
    #pragma unroll 1
    for (int ch = 0; ch < 9; ch++) {
        float acc[2][4] = {{0.f,0.f,0.f,0.f},{0.f,0.f,0.f,0.f}};
        const float* Wp = g_wq + (ch * 32 + wn * 16 + g) * 96 + t4;
        #pragma unroll
        for (int kk = 0; kk < 12; kk++) {
            #pragma unroll
            for (int ns = 0; ns < 2; ns++) {
                const float* Br = Wp + ns * 8 * 96 + kk * 8;
                mma8(acc[ns], af[kk][0], af[kk][1], af[kk][2], af[kk][3],
                     Br[0], Br[4]);
            }
        }
        int cb = (ch % 3) * 32 + wn * 16;      // column within the 96-wide Q/K/V
        int gb = (ch / 3) * 96 + cb;           // global bias index
        float* dst; int SD; float mul;
        if (ch < 3)      { dst = XW; SD = SA; mul = qscale; }
        else if (ch < 6) { dst = Kb; SD = SA; mul = 1.f; }
        else             { dst = Vb; SD = SV; mul = 1.f; }
        #pragma unroll
        for (int ns = 0; ns < 2; ns++) {
            int col = cb + ns * 8 + 2 * t4;
            float bx = b_qkv[gb + ns * 8 + 2 * t4];
            float by = b_qkv[gb + ns * 8 + 2 * t4 + 1];
            *(float2*)&dst[r0 * SD + col] =
                make_float2(tf32r((acc[ns][0] + bx) * mul), tf32r((acc[ns][1] + by) * mul));
            *(float2*)&dst[(r0 + 8) * SD + col] =
                make_float2(tf32r((acc[ns][2] + bx) * mul), tf32r((acc[ns][3] + by) * mul));
        }
    }
    __syncthreads();

    // ---- attention: per head S -> softmax -> O (O overwrites K_h cols) ----
    #pragma unroll 1
    for (int hd = 0; hd < 3; hd++) {
        const int ho = hd * 32;
        {
            float sacc[4][4] = {};
            #pragma unroll
            for (int kk = 0; kk < 4; kk++) {
                const float* Ar = XW + r0 * SA + ho + kk * 8 + t4;
                float a0 = Ar[0], a1 = Ar[8 * SA], a2 = Ar[4], a3 = Ar[8 * SA + 4];
                #pragma unroll
                for (int ns = 0; ns < 4; ns++) {
                    const float* Br = Kb + (wn * 32 + ns * 8 + g) * SA + ho + kk * 8 + t4;
                    mma8(sacc[ns], a0, a1, a2, a3, Br[0], Br[4]);
                }
            }
            #pragma unroll
            for (int ns = 0; ns < 4; ns++) {
                int col = wn * 32 + ns * 8 + 2 * t4;
                *(float2*)&Pb[r0 * SP + col]       = make_float2(sacc[ns][0], sacc[ns][1]);
                *(float2*)&Pb[(r0 + 8) * SP + col] = make_float2(sacc[ns][2], sacc[ns][3]);
            }
        }
        __syncthreads();
        {
            int tk = tid >> 2, s = tid & 3;
            float mx = -1e30f;
            for (int j = s; j < 64; j += 4) mx = fmaxf(mx, Pb[tk * SP + j]);
            mx = fmaxf(mx, __shfl_xor_sync(0xffffffffu, mx, 1));
            mx = fmaxf(mx, __shfl_xor_sync(0xffffffffu, mx, 2));
            float sum = 0.f;
            for (int j = s; j < 64; j += 4) {
                float p = __expf(Pb[tk * SP + j] - mx);
                Pb[tk * SP + j] = p;
                sum += p;
            }
            sum += __shfl_xor_sync(0xffffffffu, sum, 1);
            sum += __shfl_xor_sync(0xffffffffu, sum, 2);
            float inv = 1.0f / sum;
            for (int j = s; j < 64; j += 4)
                Pb[tk * SP + j] = tf32r(Pb[tk * SP + j] * inv);
        }
        __syncthreads();
        {
            float oacc[2][4] = {};
            #pragma unroll
            for (int kk = 0; kk < 8; kk++) {
                const float* Ar = Pb + r0 * SP + kk * 8 + t4;
                float a0 = Ar[0], a1 = Ar[8 * SP], a2 = Ar[4], a3 = Ar[8 * SP + 4];
                #pragma unroll
                for (int ns = 0; ns < 2; ns++) {
                    const float* Br = Vb + (kk * 8 + t4) * SV + ho + wn * 16 + ns * 8 + g;
                    mma8(oacc[ns], a0, a1, a2, a3, Br[0], Br[4 * SV]);
                }
            }
            #pragma unroll
            for (int ns = 0; ns < 2; ns++) {
                int col = ho + wn * 16 + ns * 8 + 2 * t4;
                *(float2*)&Kb[r0 * SA + col] =
                    make_float2(tf32r(oacc[ns][0]), tf32r(oacc[ns][1]));
                *(float2*)&Kb[(r0 + 8) * SA + col] =
                    make_float2(tf32r(oacc[ns][2]), tf32r(oacc[ns][3]));
            }
        }
        __syncthreads();
    }

    // ---- combined out∘proj: final = O @ Wc^T + bc  (A-frags hoisted) ----
    #pragma unroll
    for (int kk = 0; kk < 12; kk++) {
        const float* Ar = Kb + r0 * SA + kk * 8 + t4;
        af[kk][0] = Ar[0];
        af[kk][1] = Ar[8 * SA];
        af[kk][2] = Ar[4];
        af[kk][3] = Ar[8 * SA + 4];
    }
    #pragma unroll 1
    for (int ch = 0; ch < 3; ch++) {
        float acc[2][4] = {{0.f,0.f,0.f,0.f},{0.f,0.f,0.f,0.f}};
        const float* Wp = g_wc + (ch * 32 + wn * 16 + g) * 96 + t4;
        #pragma unroll
        for (int kk = 0; kk < 12; kk++) {
            #pragma unroll
            for (int ns = 0; ns < 2; ns++) {
                const float* Br = Wp + ns * 8 * 96 + kk * 8;
                mma8(acc[ns], af[kk][0], af[kk][1], af[kk][2], af[kk][3],
                     Br[0], Br[4]);
            }
        }
        #pragma unroll
        for (int ns = 0; ns < 2; ns++) {
            int col = ch * 32 + wn * 16 + ns * 8 + 2 * t4;
            float bx = g_bc[col], by = g_bc[col + 1];
            *(float2*)&XW[r0 * SA + col] =
                make_float2(acc[ns][0] + bx, acc[ns][1] + by);
            *(float2*)&XW[(r0 + 8) * SA + col] =
                make_float2(acc[ns][2] + bx, acc[ns][3] + by);
        }
    }
    __syncthreads();

    // ---- scatter (roll folded) ----
    for (int li = tid; li < 64 * 96; li += 256) {
        int tk = li & 63, c = li >> 6;
        int hh = (h0 + (tk >> 3) + 4) & 255;
        int wc = (w0 + (tk & 7) + 4) & 255;
        out[((b * 96 + c) * 256 + hh) * 256 + wc] = XW[tk * SA + c];
    }
}

extern "C" void kernel_launch(void* const* d_in, const int* in_sizes, int n_in,
                              void* d_out, int out_size) {
    const float* x      = (const float*)d_in[0];
    const float* ln_g   = (const float*)d_in[1];
    const float* ln_b   = (const float*)d_in[2];
    const float* w_qkv  = (const float*)d_in[3];
    const float* b_qkv  = (const float*)d_in[4];
    const float* w_out  = (const float*)d_in[5];
    const float* b_out  = (const float*)d_in[6];
    const float* w_proj = (const float*)d_in[7];
    const float* b_proj = (const float*)d_in[8];
    float* out = (float*)d_out;

    prep_wq<<<108, 256>>>(w_qkv);
    combine_wb<<<96, 96>>>(w_out, b_out, w_proj, b_proj);
    cudaFuncSetAttribute(swin_mma3_kernel,
                         cudaFuncAttributeMaxDynamicSharedMemorySize, SMEM_BYTES);
    swin_mma3_kernel<<<8192, 256, SMEM_BYTES>>>(
        x, ln_g, ln_b, b_qkv, out);
}

// round 9
// speedup vs baseline: 1.7630x; 1.7630x over previous
#include <cuda_runtime.h>
#include <cstdint>

// Swin shifted-window attention, fused, tf32 mma.sync, 2 CTAs/SM.
// R7 smem-staged weights + R8 register-hoisted A-fragments + double-buffered
// weight staging (1 barrier/chunk). out+proj folded into Wc = w_proj@w_out.

#define SA   100
#define SV   104
#define SP   68

#define F_XW 0
#define F_K  6400
#define F_V  12800
#define F_PW 19456                 // union: P (64*68=4352) | W double buffer (2*3200)
#define SMEM_FLOATS 25856
#define SMEM_BYTES  (SMEM_FLOATS * 4)

__device__ float g_wc[96 * 96];    // tf32-rounded w_proj @ w_out
__device__ float g_bc[96];         // w_proj @ b_out + b_proj

static __device__ __forceinline__ float tf32r(float x) {
    float y; asm("cvt.rna.tf32.f32 %0, %1;" : "=f"(y) : "f"(x)); return y;
}
static __device__ __forceinline__ void mma8(float* d, float a0, float a1,
                                            float a2, float a3,
                                            float b0, float b1) {
    asm volatile(
        "mma.sync.aligned.m16n8k8.row.col.f32.tf32.tf32.f32 "
        "{%0,%1,%2,%3}, {%4,%5,%6,%7}, {%8,%9}, {%0,%1,%2,%3};"
        : "+f"(d[0]), "+f"(d[1]), "+f"(d[2]), "+f"(d[3])
        : "r"(__float_as_uint(a0)), "r"(__float_as_uint(a1)),
          "r"(__float_as_uint(a2)), "r"(__float_as_uint(a3)),
          "r"(__float_as_uint(b0)), "r"(__float_as_uint(b1)));
}

__global__ void combine_wb(const float* __restrict__ w_out, const float* __restrict__ b_out,
                           const float* __restrict__ w_proj, const float* __restrict__ b_proj) {
    int row = blockIdx.x, col = threadIdx.x;
    float s = 0.f;
    #pragma unroll 4
    for (int k = 0; k < 96; k++) s += w_proj[row * 96 + k] * w_out[k * 96 + col];
    g_wc[row * 96 + col] = tf32r(s);
    if (col == 0) {
        float bs = b_proj[row];
        for (int k = 0; k < 96; k++) bs += w_proj[row * 96 + k] * b_out[k];
        g_bc[row] = bs;
    }
}

__global__ __launch_bounds__(256, 2)
void swin_mma4_kernel(const float* __restrict__ x,
                      const float* __restrict__ ln_g, const float* __restrict__ ln_b,
                      const float* __restrict__ w_qkv, const float* __restrict__ b_qkv,
                      float* __restrict__ out)
{
    extern __shared__ float sm[];
    float* XW = sm + F_XW;   // x -> y -> Q -> final result
    float* Kb = sm + F_K;    // K -> O (per-head columns)
    float* Vb = sm + F_V;    // V
    float* Pb = sm + F_PW;   // S/P (attention)  | W double buffer (GEMM staging)

    const int tid  = threadIdx.x;
    const int wid  = tid >> 5;
    const int lane = tid & 31;
    const int g    = lane >> 2;
    const int t4   = lane & 3;
    const int wm   = wid & 3;
    const int wn   = wid >> 2;

    const int wb = blockIdx.x;
    const int b  = wb >> 10;
    const int wy = (wb >> 5) & 31, wx = wb & 31;
    const int h0 = wy * 8, w0 = wx * 8;

    // ---- gather (roll folded) ----
    for (int li = tid; li < 64 * 96; li += 256) {
        int tk = li & 63, c = li >> 6;
        int hh = (h0 + (tk >> 3) + 4) & 255;
        int wc = (w0 + (tk & 7) + 4) & 255;
        XW[tk * SA + c] = x[((b * 96 + c) * 256 + hh) * 256 + wc];
    }
    __syncthreads();

    // ---- LayerNorm (4 lanes/token), write back tf32 ----
    {
        int tk = tid >> 2, s = tid & 3;
        float sum = 0.f, sq = 0.f;
        for (int c = s; c < 96; c += 4) {
            float v = XW[tk * SA + c];
            sum += v; sq += v * v;
        }
        sum += __shfl_xor_sync(0xffffffffu, sum, 1);
        sum += __shfl_xor_sync(0xffffffffu, sum, 2);
        sq  += __shfl_xor_sync(0xffffffffu, sq, 1);
        sq  += __shfl_xor_sync(0xffffffffu, sq, 2);
        float mu = sum * (1.f / 96.f);
        float rs = rsqrtf(sq * (1.f / 96.f) - mu * mu + 1e-5f);
        for (int c = s; c < 96; c += 4) {
            float v = XW[tk * SA + c];
            XW[tk * SA + c] = tf32r((v - mu) * rs * ln_g[c] + ln_b[c]);
        }
    }
    __syncthreads();

    const float qscale = 0.17677669529663687f;  // 1/sqrt(32)
    const int   r0 = wm * 16 + g;

    // ---- snapshot A-fragments of y (reused across all 9 QKV chunks) ----
    float af[12][4];
    #pragma unroll
    for (int kk = 0; kk < 12; kk++) {
        const float* Ar = XW + r0 * SA + kk * 8 + t4;
        af[kk][0] = Ar[0];
        af[kk][1] = Ar[8 * SA];
        af[kk][2] = Ar[4];
        af[kk][3] = Ar[8 * SA + 4];
    }
    __syncthreads();   // all warps hold y frags; XW may now be overwritten by Q

    // ---- QKV: 9 chunks of 32 features; double-buffered weight staging ----
    #pragma unroll 1
    for (int ch = 0; ch < 9; ch++) {
        float* Wb = Pb + (ch & 1) * 3200;
        for (int li = tid; li < 32 * 24; li += 256) {
            int row = li / 24, kc = (li % 24) * 4;
            float4 v = *(const float4*)(w_qkv + (ch * 32 + row) * 96 + kc);
            v.x = tf32r(v.x); v.y = tf32r(v.y); v.z = tf32r(v.z); v.w = tf32r(v.w);
            *(float4*)&Wb[row * SA + kc] = v;
        }
        __syncthreads();
        float acc[2][4] = {{0.f,0.f,0.f,0.f},{0.f,0.f,0.f,0.f}};
        #pragma unroll
        for (int kk = 0; kk < 12; kk++) {
            #pragma unroll
            for (int ns = 0; ns < 2; ns++) {
                const float* Br = Wb + (wn * 16 + ns * 8 + g) * SA + kk * 8 + t4;
                mma8(acc[ns], af[kk][0], af[kk][1], af[kk][2], af[kk][3],
                     Br[0], Br[4]);
            }
        }
        int cb = (ch % 3) * 32 + wn * 16;
        int gb = (ch / 3) * 96 + cb;
        float* dst; int SD; float mul;
        if (ch < 3)      { dst = XW; SD = SA; mul = qscale; }
        else if (ch < 6) { dst = Kb; SD = SA; mul = 1.f; }
        else             { dst = Vb; SD = SV; mul = 1.f; }
        #pragma unroll
        for (int ns = 0; ns < 2; ns++) {
            int col = cb + ns * 8 + 2 * t4;
            float bx = b_qkv[gb + ns * 8 + 2 * t4];
            float by = b_qkv[gb + ns * 8 + 2 * t4 + 1];
            *(float2*)&dst[r0 * SD + col] =
                make_float2(tf32r((acc[ns][0] + bx) * mul), tf32r((acc[ns][1] + by) * mul));
            *(float2*)&dst[(r0 + 8) * SD + col] =
                make_float2(tf32r((acc[ns][2] + bx) * mul), tf32r((acc[ns][3] + by) * mul));
        }
    }
    __syncthreads();

    // ---- attention: per head S -> softmax -> O (O overwrites K_h cols) ----
    #pragma unroll 1
    for (int hd = 0; hd < 3; hd++) {
        const int ho = hd * 32;
        {
            float sacc[4][4] = {};
            #pragma unroll
            for (int kk = 0; kk < 4; kk++) {
                const float* Ar = XW + r0 * SA + ho + kk * 8 + t4;
                float a0 = Ar[0], a1 = Ar[8 * SA], a2 = Ar[4], a3 = Ar[8 * SA + 4];
                #pragma unroll
                for (int ns = 0; ns < 4; ns++) {
                    const float* Br = Kb + (wn * 32 + ns * 8 + g) * SA + ho + kk * 8 + t4;
                    mma8(sacc[ns], a0, a1, a2, a3, Br[0], Br[4]);
                }
            }
            #pragma unroll
            for (int ns = 0; ns < 4; ns++) {
                int col = wn * 32 + ns * 8 + 2 * t4;
                *(float2*)&Pb[r0 * SP + col]       = make_float2(sacc[ns][0], sacc[ns][1]);
                *(float2*)&Pb[(r0 + 8) * SP + col] = make_float2(sacc[ns][2], sacc[ns][3]);
            }
        }
        __syncthreads();
        {
            int tk = tid >> 2, s = tid & 3;
            float mx = -1e30f;
            for (int j = s; j < 64; j += 4) mx = fmaxf(mx, Pb[tk * SP + j]);
            mx = fmaxf(mx, __shfl_xor_sync(0xffffffffu, mx, 1));
            mx = fmaxf(mx, __shfl_xor_sync(0xffffffffu, mx, 2));
            float sum = 0.f;
            for (int j = s; j < 64; j += 4) {
                float p = __expf(Pb[tk * SP + j] - mx);
                Pb[tk * SP + j] = p;
                sum += p;
            }
            sum += __shfl_xor_sync(0xffffffffu, sum, 1);
            sum += __shfl_xor_sync(0xffffffffu, sum, 2);
            float inv = 1.0f / sum;
            for (int j = s; j < 64; j += 4)
                Pb[tk * SP + j] = tf32r(Pb[tk * SP + j] * inv);
        }
        __syncthreads();
        {
            float oacc[2][4] = {};
            #pragma unroll
            for (int kk = 0; kk < 8; kk++) {
                const float* Ar = Pb + r0 * SP + kk * 8 + t4;
                float a0 = Ar[0], a1 = Ar[8 * SP], a2 = Ar[4], a3 = Ar[8 * SP + 4];
                #pragma unroll
                for (int ns = 0; ns < 2; ns++) {
                    const float* Br = Vb + (kk * 8 + t4) * SV + ho + wn * 16 + ns * 8 + g;
                    mma8(oacc[ns], a0, a1, a2, a3, Br[0], Br[4 * SV]);
                }
            }
            #pragma unroll
            for (int ns = 0; ns < 2; ns++) {
                int col = ho + wn * 16 + ns * 8 + 2 * t4;
                *(float2*)&Kb[r0 * SA + col] =
                    make_float2(tf32r(oacc[ns][0]), tf32r(oacc[ns][1]));
                *(float2*)&Kb[(r0 + 8) * SA + col] =
                    make_float2(tf32r(oacc[ns][2]), tf32r(oacc[ns][3]));
            }
        }
        __syncthreads();
    }

    // ---- combined out∘proj: final = O @ Wc^T + bc ----
    #pragma unroll
    for (int kk = 0; kk < 12; kk++) {
        const float* Ar = Kb + r0 * SA + kk * 8 + t4;
        af[kk][0] = Ar[0];
        af[kk][1] = Ar[8 * SA];
        af[kk][2] = Ar[4];
        af[kk][3] = Ar[8 * SA + 4];
    }
    #pragma unroll 1
    for (int ch = 0; ch < 3; ch++) {
        float* Wb = Pb + (ch & 1) * 3200;
        for (int li = tid; li < 32 * 24; li += 256) {
            int row = li / 24, kc = (li % 24) * 4;
            *(float4*)&Wb[row * SA + kc] = *(const float4*)(g_wc + (ch * 32 + row) * 96 + kc);
        }
        __syncthreads();
        float acc[2][4] = {{0.f,0.f,0.f,0.f},{0.f,0.f,0.f,0.f}};
        #pragma unroll
        for (int kk = 0; kk < 12; kk++) {
            #pragma unroll
            for (int ns = 0; ns < 2; ns++) {
                const float* Br = Wb + (wn * 16 + ns * 8 + g) * SA + kk * 8 + t4;
                mma8(acc[ns], af[kk][0], af[kk][1], af[kk][2], af[kk][3],
                     Br[0], Br[4]);
            }
        }
        #pragma unroll
        for (int ns = 0; ns < 2; ns++) {
            int col = ch * 32 + wn * 16 + ns * 8 + 2 * t4;
            float bx = g_bc[col], by = g_bc[col + 1];
            *(float2*)&XW[r0 * SA + col] =
                make_float2(acc[ns][0] + bx, acc[ns][1] + by);
            *(float2*)&XW[(r0 + 8) * SA + col] =
                make_float2(acc[ns][2] + bx, acc[ns][3] + by);
        }
    }
    __syncthreads();

    // ---- scatter (roll folded) ----
    for (int li = tid; li < 64 * 96; li += 256) {
        int tk = li & 63, c = li >> 6;
        int hh = (h0 + (tk >> 3) + 4) & 255;
        int wc = (w0 + (tk & 7) + 4) & 255;
        out[((b * 96 + c) * 256 + hh) * 256 + wc] = XW[tk * SA + c];
    }
}

extern "C" void kernel_launch(void* const* d_in, const int* in_sizes, int n_in,
                              void* d_out, int out_size) {
    const float* x      = (const float*)d_in[0];
    const float* ln_g   = (const float*)d_in[1];
    const float* ln_b   = (const float*)d_in[2];
    const float* w_qkv  = (const float*)d_in[3];
    const float* b_qkv  = (const float*)d_in[4];
    const float* w_out  = (const float*)d_in[5];
    const float* b_out  = (const float*)d_in[6];
    const float* w_proj = (const float*)d_in[7];
    const float* b_proj = (const float*)d_in[8];
    float* out = (float*)d_out;

    combine_wb<<<96, 96>>>(w_out, b_out, w_proj, b_proj);
    cudaFuncSetAttribute(swin_mma4_kernel,
                         cudaFuncAttributeMaxDynamicSharedMemorySize, SMEM_BYTES);
    swin_mma4_kernel<<<8192, 256, SMEM_BYTES>>>(
        x, ln_g, ln_b, w_qkv, b_qkv, out);
}

// round 11
// speedup vs baseline: 1.8686x; 1.0599x over previous
#include <cuda_runtime.h>
#include <cstdint>

// Swin shifted-window attention, fused, tf32 mma.sync, 2 CTAs/SM.
// R9 GEMM structure + register-resident attention: S computed 16x64 per warp
// (4 warps), softmax via shfl_xor in registers, P->A-fragment conversion via
// lane shuffles. No P smem, no softmax smem, 4 attention barriers instead of 9.

#define SA   100
#define SV   104

#define F_XW 0
#define F_K  6400
#define F_V  12800
#define F_W  19456                 // W double buffer (2*3200)
#define SMEM_FLOATS 25856
#define SMEM_BYTES  (SMEM_FLOATS * 4)

__device__ float g_wc[96 * 96];    // tf32-rounded w_proj @ w_out
__device__ float g_bc[96];         // w_proj @ b_out + b_proj

static __device__ __forceinline__ float tf32r(float x) {
    float y; asm("cvt.rna.tf32.f32 %0, %1;" : "=f"(y) : "f"(x)); return y;
}
static __device__ __forceinline__ void mma8(float* d, float a0, float a1,
                                            float a2, float a3,
                                            float b0, float b1) {
    asm volatile(
        "mma.sync.aligned.m16n8k8.row.col.f32.tf32.tf32.f32 "
        "{%0,%1,%2,%3}, {%4,%5,%6,%7}, {%8,%9}, {%0,%1,%2,%3};"
        : "+f"(d[0]), "+f"(d[1]), "+f"(d[2]), "+f"(d[3])
        : "r"(__float_as_uint(a0)), "r"(__float_as_uint(a1)),
          "r"(__float_as_uint(a2)), "r"(__float_as_uint(a3)),
          "r"(__float_as_uint(b0)), "r"(__float_as_uint(b1)));
}

__global__ void combine_wb(const float* __restrict__ w_out, const float* __restrict__ b_out,
                           const float* __restrict__ w_proj, const float* __restrict__ b_proj) {
    int row = blockIdx.x, col = threadIdx.x;
    float s = 0.f;
    #pragma unroll 4
    for (int k = 0; k < 96; k++) s += w_proj[row * 96 + k] * w_out[k * 96 + col];
    g_wc[row * 96 + col] = tf32r(s);
    if (col == 0) {
        float bs = b_proj[row];
        for (int k = 0; k < 96; k++) bs += w_proj[row * 96 + k] * b_out[k];
        g_bc[row] = bs;
    }
}

__global__ __launch_bounds__(256, 2)
void swin_mma5_kernel(const float* __restrict__ x,
                      const float* __restrict__ ln_g, const float* __restrict__ ln_b,
                      const float* __restrict__ w_qkv, const float* __restrict__ b_qkv,
                      float* __restrict__ out)
{
    extern __shared__ float sm[];
    float* XW = sm + F_XW;   // x -> y -> Q -> final result
    float* Kb = sm + F_K;    // K -> O (per-head columns)
    float* Vb = sm + F_V;    // V
    float* Wst = sm + F_W;   // weight staging double buffer

    const int tid  = threadIdx.x;
    const int wid  = tid >> 5;
    const int lane = tid & 31;
    const int g    = lane >> 2;
    const int t4   = lane & 3;
    const int wm   = wid & 3;
    const int wn   = wid >> 2;

    const int wb = blockIdx.x;
    const int b  = wb >> 10;
    const int wy = (wb >> 5) & 31, wx = wb & 31;
    const int h0 = wy * 8, w0 = wx * 8;

    // ---- gather (roll folded) ----
    for (int li = tid; li < 64 * 96; li += 256) {
        int tk = li & 63, c = li >> 6;
        int hh = (h0 + (tk >> 3) + 4) & 255;
        int wc = (w0 + (tk & 7) + 4) & 255;
        XW[tk * SA + c] = x[((b * 96 + c) * 256 + hh) * 256 + wc];
    }
    __syncthreads();

    // ---- LayerNorm (4 lanes/token), write back tf32 ----
    {
        int tk = tid >> 2, s = tid & 3;
        float sum = 0.f, sq = 0.f;
        for (int c = s; c < 96; c += 4) {
            float v = XW[tk * SA + c];
            sum += v; sq += v * v;
        }
        sum += __shfl_xor_sync(0xffffffffu, sum, 1);
        sum += __shfl_xor_sync(0xffffffffu, sum, 2);
        sq  += __shfl_xor_sync(0xffffffffu, sq, 1);
        sq  += __shfl_xor_sync(0xffffffffu, sq, 2);
        float mu = sum * (1.f / 96.f);
        float rs = rsqrtf(sq * (1.f / 96.f) - mu * mu + 1e-5f);
        for (int c = s; c < 96; c += 4) {
            float v = XW[tk * SA + c];
            XW[tk * SA + c] = tf32r((v - mu) * rs * ln_g[c] + ln_b[c]);
        }
    }
    __syncthreads();

    const float qscale = 0.17677669529663687f;  // 1/sqrt(32)
    const int   r0 = wm * 16 + g;

    // ---- snapshot A-fragments of y (reused across all 9 QKV chunks) ----
    float af[12][4];
    #pragma unroll
    for (int kk = 0; kk < 12; kk++) {
        const float* Ar = XW + r0 * SA + kk * 8 + t4;
        af[kk][0] = Ar[0];
        af[kk][1] = Ar[8 * SA];
        af[kk][2] = Ar[4];
        af[kk][3] = Ar[8 * SA + 4];
    }
    __syncthreads();   // all warps hold y frags; XW may now be overwritten by Q

    // ---- QKV: 9 chunks of 32 features; double-buffered weight staging ----
    #pragma unroll 1
    for (int ch = 0; ch < 9; ch++) {
        float* Wb = Wst + (ch & 1) * 3200;
        for (int li = tid; li < 32 * 24; li += 256) {
            int row = li / 24, kc = (li % 24) * 4;
            float4 v = *(const float4*)(w_qkv + (ch * 32 + row) * 96 + kc);
            v.x = tf32r(v.x); v.y = tf32r(v.y); v.z = tf32r(v.z); v.w = tf32r(v.w);
            *(float4*)&Wb[row * SA + kc] = v;
        }
        __syncthreads();
        float acc[2][4] = {{0.f,0.f,0.f,0.f},{0.f,0.f,0.f,0.f}};
        #pragma unroll
        for (int kk = 0; kk < 12; kk++) {
            #pragma unroll
            for (int ns = 0; ns < 2; ns++) {
                const float* Br = Wb + (wn * 16 + ns * 8 + g) * SA + kk * 8 + t4;
                mma8(acc[ns], af[kk][0], af[kk][1], af[kk][2], af[kk][3],
                     Br[0], Br[4]);
            }
        }
        int cb = (ch % 3) * 32 + wn * 16;
        int gb = (ch / 3) * 96 + cb;
        float* dst; int SD; float mul;
        if (ch < 3)      { dst = XW; SD = SA; mul = qscale; }
        else if (ch < 6) { dst = Kb; SD = SA; mul = 1.f; }
        else             { dst = Vb; SD = SV; mul = 1.f; }
        #pragma unroll
        for (int ns = 0; ns < 2; ns++) {
            int col = cb + ns * 8 + 2 * t4;
            float bx = b_qkv[gb + ns * 8 + 2 * t4];
            float by = b_qkv[gb + ns * 8 + 2 * t4 + 1];
            *(float2*)&dst[r0 * SD + col] =
                make_float2(tf32r((acc[ns][0] + bx) * mul), tf32r((acc[ns][1] + by) * mul));
            *(float2*)&dst[(r0 + 8) * SD + col] =
                make_float2(tf32r((acc[ns][2] + bx) * mul), tf32r((acc[ns][3] + by) * mul));
        }
    }
    __syncthreads();

    // ---- attention: register-resident softmax, 4 active warps (16 rows each) --
    #pragma unroll 1
    for (int hd = 0; hd < 3; hd++) {
        const int ho = hd * 32;
        float sacc[8][4];
        if (wid < 4) {
            #pragma unroll
            for (int ns = 0; ns < 8; ns++)
                #pragma unroll
                for (int j = 0; j < 4; j++) sacc[ns][j] = 0.f;
            const int sr = wid * 16 + g;
            // S = Q_h @ K_h^T : warp tile 16 x 64, K = 32
            #pragma unroll
            for (int kk = 0; kk < 4; kk++) {
                const float* Ar = XW + sr * SA + ho + kk * 8 + t4;
                float a0 = Ar[0], a1 = Ar[8 * SA], a2 = Ar[4], a3 = Ar[8 * SA + 4];
                #pragma unroll
                for (int ns = 0; ns < 8; ns++) {
                    const float* Br = Kb + (ns * 8 + g) * SA + ho + kk * 8 + t4;
                    mma8(sacc[ns], a0, a1, a2, a3, Br[0], Br[4]);
                }
            }
        }
        __syncthreads();   // all S reads of Kb done before O writes below
        if (wid < 4) {
            // softmax rows sr (lo: elems 0,1) and sr+8 (hi: elems 2,3)
            float mxlo = -1e30f, mxhi = -1e30f;
            #pragma unroll
            for (int ns = 0; ns < 8; ns++) {
                mxlo = fmaxf(mxlo, fmaxf(sacc[ns][0], sacc[ns][1]));
                mxhi = fmaxf(mxhi, fmaxf(sacc[ns][2], sacc[ns][3]));
            }
            mxlo = fmaxf(mxlo, __shfl_xor_sync(0xffffffffu, mxlo, 1));
            mxlo = fmaxf(mxlo, __shfl_xor_sync(0xffffffffu, mxlo, 2));
            mxhi = fmaxf(mxhi, __shfl_xor_sync(0xffffffffu, mxhi, 1));
            mxhi = fmaxf(mxhi, __shfl_xor_sync(0xffffffffu, mxhi, 2));
            float slo = 0.f, shi = 0.f;
            #pragma unroll
            for (int ns = 0; ns < 8; ns++) {
                sacc[ns][0] = __expf(sacc[ns][0] - mxlo);
                sacc[ns][1] = __expf(sacc[ns][1] - mxlo);
                sacc[ns][2] = __expf(sacc[ns][2] - mxhi);
                sacc[ns][3] = __expf(sacc[ns][3] - mxhi);
                slo += sacc[ns][0] + sacc[ns][1];
                shi += sacc[ns][2] + sacc[ns][3];
            }
            slo += __shfl_xor_sync(0xffffffffu, slo, 1);
            slo += __shfl_xor_sync(0xffffffffu, slo, 2);
            shi += __shfl_xor_sync(0xffffffffu, shi, 1);
            shi += __shfl_xor_sync(0xffffffffu, shi, 2);
            float ilo = 1.f / slo, ihi = 1.f / shi;
            #pragma unroll
            for (int ns = 0; ns < 8; ns++) {
                sacc[ns][0] = tf32r(sacc[ns][0] * ilo);
                sacc[ns][1] = tf32r(sacc[ns][1] * ilo);
                sacc[ns][2] = tf32r(sacc[ns][2] * ihi);
                sacc[ns][3] = tf32r(sacc[ns][3] * ihi);
            }
            // O_h = P @ V_h : convert P C-frags -> A-frags via shuffles
            const int sr   = wid * 16 + g;
            const int srcA = (g << 2) | (t4 >> 1);
            const int srcB = srcA + 2;
            const int sel  = t4 & 1;
            float oacc[4][4];
            #pragma unroll
            for (int ns = 0; ns < 4; ns++)
                #pragma unroll
                for (int j = 0; j < 4; j++) oacc[ns][j] = 0.f;
            #pragma unroll
            for (int kk = 0; kk < 8; kk++) {
                float v0 = __shfl_sync(0xffffffffu, sacc[kk][0], srcA);
                float v1 = __shfl_sync(0xffffffffu, sacc[kk][1], srcA);
                float v2 = __shfl_sync(0xffffffffu, sacc[kk][2], srcA);
                float v3 = __shfl_sync(0xffffffffu, sacc[kk][3], srcA);
                float w0_ = __shfl_sync(0xffffffffu, sacc[kk][0], srcB);
                float w1_ = __shfl_sync(0xffffffffu, sacc[kk][1], srcB);
                float w2_ = __shfl_sync(0xffffffffu, sacc[kk][2], srcB);
                float w3_ = __shfl_sync(0xffffffffu, sacc[kk][3], srcB);
                float a0 = sel ? v1 : v0;
                float a1 = sel ? v3 : v2;
                float a2 = sel ? w1_ : w0_;
                float a3 = sel ? w3_ : w2_;
                #pragma unroll
                for (int ns = 0; ns < 4; ns++) {
                    const float* Br = Vb + (kk * 8 + t4) * SV + ho + ns * 8 + g;
                    mma8(oacc[ns], a0, a1, a2, a3, Br[0], Br[4 * SV]);
                }
            }
            // write O into the dead K_h columns of Kb
            #pragma unroll
            for (int ns = 0; ns < 4; ns++) {
                int col = ho + ns * 8 + 2 * t4;
                *(float2*)&Kb[sr * SA + col] =
                    make_float2(tf32r(oacc[ns][0]), tf32r(oacc[ns][1]));
                *(float2*)&Kb[(sr + 8) * SA + col] =
                    make_float2(tf32r(oacc[ns][2]), tf32r(oacc[ns][3]));
            }
        }
    }
    __syncthreads();

    // ---- combined out∘proj: final = O @ Wc^T + bc ----
    #pragma unroll
    for (int kk = 0; kk < 12; kk++) {
        const float* Ar = Kb + r0 * SA + kk * 8 + t4;
        af[kk][0] = Ar[0];
        af[kk][1] = Ar[8 * SA];
        af[kk][2] = Ar[4];
        af[kk][3] = Ar[8 * SA + 4];
    }
    #pragma unroll 1
    for (int ch = 0; ch < 3; ch++) {
        float* Wb = Wst + (ch & 1) * 3200;
        for (int li = tid; li < 32 * 24; li += 256) {
            int row = li / 24, kc = (li % 24) * 4;
            *(float4*)&Wb[row * SA + kc] = *(const float4*)(g_wc + (ch * 32 + row) * 96 + kc);
        }
        __syncthreads();
        float acc[2][4] = {{0.f,0.f,0.f,0.f},{0.f,0.f,0.f,0.f}};
        #pragma unroll
        for (int kk = 0; kk < 12; kk++) {
            #pragma unroll
            for (int ns = 0; ns < 2; ns++) {
                const float* Br = Wb + (wn * 16 + ns * 8 + g) * SA + kk * 8 + t4;
                mma8(acc[ns], af[kk][0], af[kk][1], af[kk][2], af[kk][3],
                     Br[0], Br[4]);
            }
        }
        #pragma unroll
        for (int ns = 0; ns < 2; ns++) {
            int col = ch * 32 + wn * 16 + ns * 8 + 2 * t4;
            float bx = g_bc[col], by = g_bc[col + 1];
            *(float2*)&XW[r0 * SA + col] =
                make_float2(acc[ns][0] + bx, acc[ns][1] + by);
            *(float2*)&XW[(r0 + 8) * SA + col] =
                make_float2(acc[ns][2] + bx, acc[ns][3] + by);
        }
    }
    __syncthreads();

    // ---- scatter (roll folded) ----
    for (int li = tid; li < 64 * 96; li += 256) {
        int tk = li & 63, c = li >> 6;
        int hh = (h0 + (tk >> 3) + 4) & 255;
        int wc = (w0 + (tk & 7) + 4) & 255;
        out[((b * 96 + c) * 256 + hh) * 256 + wc] = XW[tk * SA + c];
    }
}

extern "C" void kernel_launch(void* const* d_in, const int* in_sizes, int n_in,
                              void* d_out, int out_size) {
    const float* x      = (const float*)d_in[0];
    const float* ln_g   = (const float*)d_in[1];
    const float* ln_b   = (const float*)d_in[2];
    const float* w_qkv  = (const float*)d_in[3];
    const float* b_qkv  = (const float*)d_in[4];
    const float* w_out  = (const float*)d_in[5];
    const float* b_out  = (const float*)d_in[6];
    const float* w_proj = (const float*)d_in[7];
    const float* b_proj = (const float*)d_in[8];
    float* out = (float*)d_out;

    combine_wb<<<96, 96>>>(w_out, b_out, w_proj, b_proj);
    cudaFuncSetAttribute(swin_mma5_kernel,
                         cudaFuncAttributeMaxDynamicSharedMemorySize, SMEM_BYTES);
    swin_mma5_kernel<<<8192, 256, SMEM_BYTES>>>(
        x, ln_g, ln_b, w_qkv, b_qkv, out);
}

// round 12
// speedup vs baseline: 1.8827x; 1.0075x over previous
#include <cuda_runtime.h>
#include <cstdint>

// Swin shifted-window attention, fused, tf32 mma.sync, 2 CTAs/SM.
// Head-parallel zero-barrier attention: pass0 = heads 0,1 on warps 0-3 / 4-7;
// pass1 = head 2 on warps 0-3. O overwrites own-head Q columns in XW (own rows
// only -> no races, no barriers). Final GEMM reads O from XW, writes Kb.

#define SA   100
#define SV   104

#define F_XW 0
#define F_K  6400
#define F_V  12800
#define F_W  19456                 // W double buffer (2*3200)
#define SMEM_FLOATS 25856
#define SMEM_BYTES  (SMEM_FLOATS * 4)

__device__ float g_wc[96 * 96];    // tf32-rounded w_proj @ w_out
__device__ float g_bc[96];         // w_proj @ b_out + b_proj

static __device__ __forceinline__ float tf32r(float x) {
    float y; asm("cvt.rna.tf32.f32 %0, %1;" : "=f"(y) : "f"(x)); return y;
}
static __device__ __forceinline__ void mma8(float* d, float a0, float a1,
                                            float a2, float a3,
                                            float b0, float b1) {
    asm volatile(
        "mma.sync.aligned.m16n8k8.row.col.f32.tf32.tf32.f32 "
        "{%0,%1,%2,%3}, {%4,%5,%6,%7}, {%8,%9}, {%0,%1,%2,%3};"
        : "+f"(d[0]), "+f"(d[1]), "+f"(d[2]), "+f"(d[3])
        : "r"(__float_as_uint(a0)), "r"(__float_as_uint(a1)),
          "r"(__float_as_uint(a2)), "r"(__float_as_uint(a3)),
          "r"(__float_as_uint(b0)), "r"(__float_as_uint(b1)));
}

__global__ void combine_wb(const float* __restrict__ w_out, const float* __restrict__ b_out,
                           const float* __restrict__ w_proj, const float* __restrict__ b_proj) {
    int row = blockIdx.x, col = threadIdx.x;
    float s = 0.f;
    #pragma unroll 4
    for (int k = 0; k < 96; k++) s += w_proj[row * 96 + k] * w_out[k * 96 + col];
    g_wc[row * 96 + col] = tf32r(s);
    if (col == 0) {
        float bs = b_proj[row];
        for (int k = 0; k < 96; k++) bs += w_proj[row * 96 + k] * b_out[k];
        g_bc[row] = bs;
    }
}

// One head for one 16-row strip: S = Q_h K_h^T, softmax (registers),
// O = P V_h written over the Q_h columns of XW (own rows only).
static __device__ __forceinline__ void attn_head(float* __restrict__ XW,
                                                 const float* __restrict__ Kb,
                                                 const float* __restrict__ Vb,
                                                 int ho, int ws, int g, int t4)
{
    const int sr = ws * 16 + g;
    float sacc[8][4];
    #pragma unroll
    for (int ns = 0; ns < 8; ns++)
        #pragma unroll
        for (int j = 0; j < 4; j++) sacc[ns][j] = 0.f;

    // S: 16 x 64, K = 32
    #pragma unroll
    for (int kk = 0; kk < 4; kk++) {
        const float* Ar = XW + sr * SA + ho + kk * 8 + t4;
        float a0 = Ar[0], a1 = Ar[8 * SA], a2 = Ar[4], a3 = Ar[8 * SA + 4];
        #pragma unroll
        for (int ns = 0; ns < 8; ns++) {
            const float* Br = Kb + (ns * 8 + g) * SA + ho + kk * 8 + t4;
            mma8(sacc[ns], a0, a1, a2, a3, Br[0], Br[4]);
        }
    }
    // softmax: rows sr (elems 0,1) and sr+8 (elems 2,3)
    float mxlo = -1e30f, mxhi = -1e30f;
    #pragma unroll
    for (int ns = 0; ns < 8; ns++) {
        mxlo = fmaxf(mxlo, fmaxf(sacc[ns][0], sacc[ns][1]));
        mxhi = fmaxf(mxhi, fmaxf(sacc[ns][2], sacc[ns][3]));
    }
    mxlo = fmaxf(mxlo, __shfl_xor_sync(0xffffffffu, mxlo, 1));
    mxlo = fmaxf(mxlo, __shfl_xor_sync(0xffffffffu, mxlo, 2));
    mxhi = fmaxf(mxhi, __shfl_xor_sync(0xffffffffu, mxhi, 1));
    mxhi = fmaxf(mxhi, __shfl_xor_sync(0xffffffffu, mxhi, 2));
    float slo = 0.f, shi = 0.f;
    #pragma unroll
    for (int ns = 0; ns < 8; ns++) {
        sacc[ns][0] = __expf(sacc[ns][0] - mxlo);
        sacc[ns][1] = __expf(sacc[ns][1] - mxlo);
        sacc[ns][2] = __expf(sacc[ns][2] - mxhi);
        sacc[ns][3] = __expf(sacc[ns][3] - mxhi);
        slo += sacc[ns][0] + sacc[ns][1];
        shi += sacc[ns][2] + sacc[ns][3];
    }
    slo += __shfl_xor_sync(0xffffffffu, slo, 1);
    slo += __shfl_xor_sync(0xffffffffu, slo, 2);
    shi += __shfl_xor_sync(0xffffffffu, shi, 1);
    shi += __shfl_xor_sync(0xffffffffu, shi, 2);
    float ilo = 1.f / slo, ihi = 1.f / shi;
    #pragma unroll
    for (int ns = 0; ns < 8; ns++) {
        sacc[ns][0] = tf32r(sacc[ns][0] * ilo);
        sacc[ns][1] = tf32r(sacc[ns][1] * ilo);
        sacc[ns][2] = tf32r(sacc[ns][2] * ihi);
        sacc[ns][3] = tf32r(sacc[ns][3] * ihi);
    }
    // O = P @ V_h : P C-frags -> A-frags via lane shuffles
    const int srcA = (g << 2) | (t4 >> 1);
    const int srcB = srcA + 2;
    const int sel  = t4 & 1;
    float oacc[4][4];
    #pragma unroll
    for (int ns = 0; ns < 4; ns++)
        #pragma unroll
        for (int j = 0; j < 4; j++) oacc[ns][j] = 0.f;
    #pragma unroll
    for (int kk = 0; kk < 8; kk++) {
        float v0 = __shfl_sync(0xffffffffu, sacc[kk][0], srcA);
        float v1 = __shfl_sync(0xffffffffu, sacc[kk][1], srcA);
        float v2 = __shfl_sync(0xffffffffu, sacc[kk][2], srcA);
        float v3 = __shfl_sync(0xffffffffu, sacc[kk][3], srcA);
        float w0_ = __shfl_sync(0xffffffffu, sacc[kk][0], srcB);
        float w1_ = __shfl_sync(0xffffffffu, sacc[kk][1], srcB);
        float w2_ = __shfl_sync(0xffffffffu, sacc[kk][2], srcB);
        float w3_ = __shfl_sync(0xffffffffu, sacc[kk][3], srcB);
        float a0 = sel ? v1 : v0;
        float a1 = sel ? v3 : v2;
        float a2 = sel ? w1_ : w0_;
        float a3 = sel ? w3_ : w2_;
        #pragma unroll
        for (int ns = 0; ns < 4; ns++) {
            const float* Br = Vb + (kk * 8 + t4) * SV + ho + ns * 8 + g;
            mma8(oacc[ns], a0, a1, a2, a3, Br[0], Br[4 * SV]);
        }
    }
    // O -> XW over dead Q_h columns, own rows only
    #pragma unroll
    for (int ns = 0; ns < 4; ns++) {
        int col = ho + ns * 8 + 2 * t4;
        *(float2*)&XW[sr * SA + col] =
            make_float2(tf32r(oacc[ns][0]), tf32r(oacc[ns][1]));
        *(float2*)&XW[(sr + 8) * SA + col] =
            make_float2(tf32r(oacc[ns][2]), tf32r(oacc[ns][3]));
    }
}

__global__ __launch_bounds__(256, 2)
void swin_mma6_kernel(const float* __restrict__ x,
                      const float* __restrict__ ln_g, const float* __restrict__ ln_b,
                      const float* __restrict__ w_qkv, const float* __restrict__ b_qkv,
                      float* __restrict__ out)
{
    extern __shared__ float sm[];
    float* XW  = sm + F_XW;   // x -> y -> Q -> O
    float* Kb  = sm + F_K;    // K -> final result
    float* Vb  = sm + F_V;    // V
    float* Wst = sm + F_W;    // weight staging double buffer

    const int tid  = threadIdx.x;
    const int wid  = tid >> 5;
    const int lane = tid & 31;
    const int g    = lane >> 2;
    const int t4   = lane & 3;
    const int ws   = wid & 3;   // row strip
    const int wg   = wid >> 2;  // N-half / head group

    const int wb = blockIdx.x;
    const int b  = wb >> 10;
    const int wy = (wb >> 5) & 31, wx = wb & 31;
    const int h0 = wy * 8, w0 = wx * 8;

    // ---- gather (roll folded) ----
    for (int li = tid; li < 64 * 96; li += 256) {
        int tk = li & 63, c = li >> 6;
        int hh = (h0 + (tk >> 3) + 4) & 255;
        int wc = (w0 + (tk & 7) + 4) & 255;
        XW[tk * SA + c] = x[((b * 96 + c) * 256 + hh) * 256 + wc];
    }
    __syncthreads();

    // ---- LayerNorm (4 lanes/token), write back tf32 ----
    {
        int tk = tid >> 2, s = tid & 3;
        float sum = 0.f, sq = 0.f;
        for (int c = s; c < 96; c += 4) {
            float v = XW[tk * SA + c];
            sum += v; sq += v * v;
        }
        sum += __shfl_xor_sync(0xffffffffu, sum, 1);
        sum += __shfl_xor_sync(0xffffffffu, sum, 2);
        sq  += __shfl_xor_sync(0xffffffffu, sq, 1);
        sq  += __shfl_xor_sync(0xffffffffu, sq, 2);
        float mu = sum * (1.f / 96.f);
        float rs = rsqrtf(sq * (1.f / 96.f) - mu * mu + 1e-5f);
        for (int c = s; c < 96; c += 4) {
            float v = XW[tk * SA + c];
            XW[tk * SA + c] = tf32r((v - mu) * rs * ln_g[c] + ln_b[c]);
        }
    }
    __syncthreads();

    const float qscale = 0.17677669529663687f;  // 1/sqrt(32)
    const int   r0 = ws * 16 + g;

    // ---- snapshot A-fragments of y ----
    float af[12][4];
    #pragma unroll
    for (int kk = 0; kk < 12; kk++) {
        const float* Ar = XW + r0 * SA + kk * 8 + t4;
        af[kk][0] = Ar[0];
        af[kk][1] = Ar[8 * SA];
        af[kk][2] = Ar[4];
        af[kk][3] = Ar[8 * SA + 4];
    }
    __syncthreads();   // frags held; XW may be overwritten by Q

    // ---- QKV: 9 chunks of 32 features; double-buffered weight staging ----
    #pragma unroll 1
    for (int ch = 0; ch < 9; ch++) {
        float* Wb = Wst + (ch & 1) * 3200;
        for (int li = tid; li < 32 * 24; li += 256) {
            int row = li / 24, kc = (li % 24) * 4;
            float4 v = *(const float4*)(w_qkv + (ch * 32 + row) * 96 + kc);
            v.x = tf32r(v.x); v.y = tf32r(v.y); v.z = tf32r(v.z); v.w = tf32r(v.w);
            *(float4*)&Wb[row * SA + kc] = v;
        }
        __syncthreads();
        float acc[2][4] = {{0.f,0.f,0.f,0.f},{0.f,0.f,0.f,0.f}};
        #pragma unroll
        for (int kk = 0; kk < 12; kk++) {
            #pragma unroll
            for (int ns = 0; ns < 2; ns++) {
                const float* Br = Wb + (wg * 16 + ns * 8 + g) * SA + kk * 8 + t4;
                mma8(acc[ns], af[kk][0], af[kk][1], af[kk][2], af[kk][3],
                     Br[0], Br[4]);
            }
        }
        int cb = (ch % 3) * 32 + wg * 16;
        int gb = (ch / 3) * 96 + cb;
        float* dst; int SD; float mul;
        if (ch < 3)      { dst = XW; SD = SA; mul = qscale; }
        else if (ch < 6) { dst = Kb; SD = SA; mul = 1.f; }
        else             { dst = Vb; SD = SV; mul = 1.f; }
        #pragma unroll
        for (int ns = 0; ns < 2; ns++) {
            int col = cb + ns * 8 + 2 * t4;
            float bx = b_qkv[gb + ns * 8 + 2 * t4];
            float by = b_qkv[gb + ns * 8 + 2 * t4 + 1];
            *(float2*)&dst[r0 * SD + col] =
                make_float2(tf32r((acc[ns][0] + bx) * mul), tf32r((acc[ns][1] + by) * mul));
            *(float2*)&dst[(r0 + 8) * SD + col] =
                make_float2(tf32r((acc[ns][2] + bx) * mul), tf32r((acc[ns][3] + by) * mul));
        }
    }
    __syncthreads();

    // ---- attention: head-parallel, zero barriers ----
    attn_head(XW, Kb, Vb, wg * 32, ws, g, t4);          // pass 0: heads 0,1
    if (wg == 0) attn_head(XW, Kb, Vb, 64, ws, g, t4);  // pass 1: head 2
    __syncthreads();

    // ---- combined out∘proj: final = O @ Wc^T + bc  (O in XW) -> Kb ----
    #pragma unroll
    for (int kk = 0; kk < 12; kk++) {
        const float* Ar = XW + r0 * SA + kk * 8 + t4;
        af[kk][0] = Ar[0];
        af[kk][1] = Ar[8 * SA];
        af[kk][2] = Ar[4];
        af[kk][3] = Ar[8 * SA + 4];
    }
    #pragma unroll 1
    for (int ch = 0; ch < 3; ch++) {
        float* Wb = Wst + (ch & 1) * 3200;
        for (int li = tid; li < 32 * 24; li += 256) {
            int row = li / 24, kc = (li % 24) * 4;
            *(float4*)&Wb[row * SA + kc] = *(const float4*)(g_wc + (ch * 32 + row) * 96 + kc);
        }
        __syncthreads();
        float acc[2][4] = {{0.f,0.f,0.f,0.f},{0.f,0.f,0.f,0.f}};
        #pragma unroll
        for (int kk = 0; kk < 12; kk++) {
            #pragma unroll
            for (int ns = 0; ns < 2; ns++) {
                const float* Br = Wb + (wg * 16 + ns * 8 + g) * SA + kk * 8 + t4;
                mma8(acc[ns], af[kk][0], af[kk][1], af[kk][2], af[kk][3],
                     Br[0], Br[4]);
            }
        }
        #pragma unroll
        for (int ns = 0; ns < 2; ns++) {
            int col = ch * 32 + wg * 16 + ns * 8 + 2 * t4;
            float bx = g_bc[col], by = g_bc[col + 1];
            *(float2*)&Kb[r0 * SA + col] =
                make_float2(acc[ns][0] + bx, acc[ns][1] + by);
            *(float2*)&Kb[(r0 + 8) * SA + col] =
                make_float2(acc[ns][2] + bx, acc[ns][3] + by);
        }
    }
    __syncthreads();

    // ---- scatter (roll folded) ----
    for (int li = tid; li < 64 * 96; li += 256) {
        int tk = li & 63, c = li >> 6;
        int hh = (h0 + (tk >> 3) + 4) & 255;
        int wc = (w0 + (tk & 7) + 4) & 255;
        out[((b * 96 + c) * 256 + hh) * 256 + wc] = Kb[tk * SA + c];
    }
}

extern "C" void kernel_launch(void* const* d_in, const int* in_sizes, int n_in,
                              void* d_out, int out_size) {
    const float* x      = (const float*)d_in[0];
    const float* ln_g   = (const float*)d_in[1];
    const float* ln_b   = (const float*)d_in[2];
    const float* w_qkv  = (const float*)d_in[3];
    const float* b_qkv  = (const float*)d_in[4];
    const float* w_out  = (const float*)d_in[5];
    const float* b_out  = (const float*)d_in[6];
    const float* w_proj = (const float*)d_in[7];
    const float* b_proj = (const float*)d_in[8];
    float* out = (float*)d_out;

    combine_wb<<<96, 96>>>(w_out, b_out, w_proj, b_proj);
    cudaFuncSetAttribute(swin_mma6_kernel,
                         cudaFuncAttributeMaxDynamicSharedMemorySize, SMEM_BYTES);
    swin_mma6_kernel<<<8192, 256, SMEM_BYTES>>>(
        x, ln_g, ln_b, w_qkv, b_qkv, out);
}

// round 15
// speedup vs baseline: 1.9270x; 1.0236x over previous
#include <cuda_runtime.h>
#include <cstdint>

// Swin shifted-window attention, fused, tf32 mma.sync.
// 2 windows per 512-thread CTA (grid 4096), 215KB smem, 1 CTA/SM (16 warps).
// All fixed costs (staging, barriers, index math) amortized over 2 windows.
// Wc staged once into its own region; final GEMM barrier-free.

#define SA   100
#define SV   104

#define F_XW 0
#define F_K  12800
#define F_V  25600
#define F_WQ 38912                  // qkv staging double buffer (2*3200)
#define F_WC 45312                  // combined weight, 96*100
#define SMEM_FLOATS 54912
#define SMEM_BYTES  (SMEM_FLOATS * 4)

__device__ float g_wc[96 * 96];    // tf32-rounded w_proj @ w_out
__device__ float g_bc[96];         // w_proj @ b_out + b_proj

static __device__ __forceinline__ float tf32r(float x) {
    float y; asm("cvt.rna.tf32.f32 %0, %1;" : "=f"(y) : "f"(x)); return y;
}
static __device__ __forceinline__ void mma8(float* d, float a0, float a1,
                                            float a2, float a3,
                                            float b0, float b1) {
    asm volatile(
        "mma.sync.aligned.m16n8k8.row.col.f32.tf32.tf32.f32 "
        "{%0,%1,%2,%3}, {%4,%5,%6,%7}, {%8,%9}, {%0,%1,%2,%3};"
        : "+f"(d[0]), "+f"(d[1]), "+f"(d[2]), "+f"(d[3])
        : "r"(__float_as_uint(a0)), "r"(__float_as_uint(a1)),
          "r"(__float_as_uint(a2)), "r"(__float_as_uint(a3)),
          "r"(__float_as_uint(b0)), "r"(__float_as_uint(b1)));
}

__global__ void combine_wb(const float* __restrict__ w_out, const float* __restrict__ b_out,
                           const float* __restrict__ w_proj, const float* __restrict__ b_proj) {
    int row = blockIdx.x, col = threadIdx.x;
    float s = 0.f;
    #pragma unroll 4
    for (int k = 0; k < 96; k++) s += w_proj[row * 96 + k] * w_out[k * 96 + col];
    g_wc[row * 96 + col] = tf32r(s);
    if (col == 0) {
        float bs = b_proj[row];
        for (int k = 0; k < 96; k++) bs += w_proj[row * 96 + k] * b_out[k];
        g_bc[row] = bs;
    }
}

// One head, one 16-row strip (strip lives wholly inside one window).
// S = Q_h K_h^T, softmax in registers, O = P V_h overwrites Q_h cols of XW.
static __device__ __forceinline__ void attn_head(float* __restrict__ XW,
                                                 const float* __restrict__ Kb,
                                                 const float* __restrict__ Vb,
                                                 int ho, int ws, int g, int t4)
{
    const int sr    = ws * 16 + g;
    const int wbase = (ws >> 2) * 64;       // own window's K/V row base
    float sacc[8][4];
    #pragma unroll
    for (int ns = 0; ns < 8; ns++)
        #pragma unroll
        for (int j = 0; j < 4; j++) sacc[ns][j] = 0.f;

    #pragma unroll
    for (int kk = 0; kk < 4; kk++) {
        const float* Ar = XW + sr * SA + ho + kk * 8 + t4;
        float a0 = Ar[0], a1 = Ar[8 * SA], a2 = Ar[4], a3 = Ar[8 * SA + 4];
        #pragma unroll
        for (int ns = 0; ns < 8; ns++) {
            const float* Br = Kb + (wbase + ns * 8 + g) * SA + ho + kk * 8 + t4;
            mma8(sacc[ns], a0, a1, a2, a3, Br[0], Br[4]);
        }
    }
    float mxlo = -1e30f, mxhi = -1e30f;
    #pragma unroll
    for (int ns = 0; ns < 8; ns++) {
        mxlo = fmaxf(mxlo, fmaxf(sacc[ns][0], sacc[ns][1]));
        mxhi = fmaxf(mxhi, fmaxf(sacc[ns][2], sacc[ns][3]));
    }
    mxlo = fmaxf(mxlo, __shfl_xor_sync(0xffffffffu, mxlo, 1));
    mxlo = fmaxf(mxlo, __shfl_xor_sync(0xffffffffu, mxlo, 2));
    mxhi = fmaxf(mxhi, __shfl_xor_sync(0xffffffffu, mxhi, 1));
    mxhi = fmaxf(mxhi, __shfl_xor_sync(0xffffffffu, mxhi, 2));
    float slo = 0.f, shi = 0.f;
    #pragma unroll
    for (int ns = 0; ns < 8; ns++) {
        sacc[ns][0] = __expf(sacc[ns][0] - mxlo);
        sacc[ns][1] = __expf(sacc[ns][1] - mxlo);
        sacc[ns][2] = __expf(sacc[ns][2] - mxhi);
        sacc[ns][3] = __expf(sacc[ns][3] - mxhi);
        slo += sacc[ns][0] + sacc[ns][1];
        shi += sacc[ns][2] + sacc[ns][3];
    }
    slo += __shfl_xor_sync(0xffffffffu, slo, 1);
    slo += __shfl_xor_sync(0xffffffffu, slo, 2);
    shi += __shfl_xor_sync(0xffffffffu, shi, 1);
    shi += __shfl_xor_sync(0xffffffffu, shi, 2);
    float ilo = 1.f / slo, ihi = 1.f / shi;
    #pragma unroll
    for (int ns = 0; ns < 8; ns++) {
        sacc[ns][0] = tf32r(sacc[ns][0] * ilo);
        sacc[ns][1] = tf32r(sacc[ns][1] * ilo);
        sacc[ns][2] = tf32r(sacc[ns][2] * ihi);
        sacc[ns][3] = tf32r(sacc[ns][3] * ihi);
    }
    const int srcA = (g << 2) | (t4 >> 1);
    const int srcB = srcA + 2;
    const int sel  = t4 & 1;
    float oacc[4][4];
    #pragma unroll
    for (int ns = 0; ns < 4; ns++)
        #pragma unroll
        for (int j = 0; j < 4; j++) oacc[ns][j] = 0.f;
    #pragma unroll
    for (int kk = 0; kk < 8; kk++) {
        float v0 = __shfl_sync(0xffffffffu, sacc[kk][0], srcA);
        float v1 = __shfl_sync(0xffffffffu, sacc[kk][1], srcA);
        float v2 = __shfl_sync(0xffffffffu, sacc[kk][2], srcA);
        float v3 = __shfl_sync(0xffffffffu, sacc[kk][3], srcA);
        float w0_ = __shfl_sync(0xffffffffu, sacc[kk][0], srcB);
        float w1_ = __shfl_sync(0xffffffffu, sacc[kk][1], srcB);
        float w2_ = __shfl_sync(0xffffffffu, sacc[kk][2], srcB);
        float w3_ = __shfl_sync(0xffffffffu, sacc[kk][3], srcB);
        float a0 = sel ? v1 : v0;
        float a1 = sel ? v3 : v2;
        float a2 = sel ? w1_ : w0_;
        float a3 = sel ? w3_ : w2_;
        #pragma unroll
        for (int ns = 0; ns < 4; ns++) {
            const float* Br = Vb + (wbase + kk * 8 + t4) * SV + ho + ns * 8 + g;
            mma8(oacc[ns], a0, a1, a2, a3, Br[0], Br[4 * SV]);
        }
    }
    #pragma unroll
    for (int ns = 0; ns < 4; ns++) {
        int col = ho + ns * 8 + 2 * t4;
        *(float2*)&XW[sr * SA + col] =
            make_float2(tf32r(oacc[ns][0]), tf32r(oacc[ns][1]));
        *(float2*)&XW[(sr + 8) * SA + col] =
            make_float2(tf32r(oacc[ns][2]), tf32r(oacc[ns][3]));
    }
}

__global__ __launch_bounds__(512, 1)
void swin_mma7_kernel(const float* __restrict__ x,
                      const float* __restrict__ ln_g, const float* __restrict__ ln_b,
                      const float* __restrict__ w_qkv, const float* __restrict__ b_qkv,
                      float* __restrict__ out)
{
    extern __shared__ float sm[];
    float* XW  = sm + F_XW;   // [128,SA] x -> y -> Q -> O
    float* Kb  = sm + F_K;    // [128,SA] K -> final result
    float* Vb  = sm + F_V;    // [128,SV] V
    float* Wst = sm + F_WQ;   // qkv staging double buffer
    float* WcS = sm + F_WC;   // combined weight [96,SA]

    const int tid  = threadIdx.x;
    const int wid  = tid >> 5;
    const int lane = tid & 31;
    const int g    = lane >> 2;
    const int t4   = lane & 3;
    const int ws   = wid & 7;   // row strip (16 rows); 0-3 window0, 4-7 window1
    const int wg   = wid >> 3;  // N half

    const int w2 = blockIdx.x * 2;

    // ---- gather both windows (roll folded) ----
    for (int li = tid; li < 128 * 96; li += 512) {
        int r = li & 127, c = li >> 7;
        int w = w2 + (r >> 6);
        int t = r & 63;
        int b = w >> 10, wy = (w >> 5) & 31, wx = w & 31;
        int hh = ((wy << 3) + (t >> 3) + 4) & 255;
        int wc = ((wx << 3) + (t & 7) + 4) & 255;
        XW[r * SA + c] = x[((b * 96 + c) << 16) + hh * 256 + wc];
    }
    __syncthreads();

    // ---- LayerNorm: 128 rows x 4 lanes = 512 threads exactly ----
    {
        int tk = tid >> 2, s = tid & 3;
        float sum = 0.f, sq = 0.f;
        for (int c = s; c < 96; c += 4) {
            float v = XW[tk * SA + c];
            sum += v; sq += v * v;
        }
        sum += __shfl_xor_sync(0xffffffffu, sum, 1);
        sum += __shfl_xor_sync(0xffffffffu, sum, 2);
        sq  += __shfl_xor_sync(0xffffffffu, sq, 1);
        sq  += __shfl_xor_sync(0xffffffffu, sq, 2);
        float mu = sum * (1.f / 96.f);
        float rs = rsqrtf(sq * (1.f / 96.f) - mu * mu + 1e-5f);
        for (int c = s; c < 96; c += 4) {
            float v = XW[tk * SA + c];
            XW[tk * SA + c] = tf32r((v - mu) * rs * ln_g[c] + ln_b[c]);
        }
    }
    __syncthreads();

    const float qscale = 0.17677669529663687f;  // 1/sqrt(32)
    const int   r0 = ws * 16 + g;

    // ---- snapshot A-fragments of y ----
    float af[12][4];
    #pragma unroll
    for (int kk = 0; kk < 12; kk++) {
        const float* Ar = XW + r0 * SA + kk * 8 + t4;
        af[kk][0] = Ar[0];
        af[kk][1] = Ar[8 * SA];
        af[kk][2] = Ar[4];
        af[kk][3] = Ar[8 * SA + 4];
    }
    __syncthreads();

    // ---- QKV: 9 chunks of 32 features; double-buffered staging ----
    #pragma unroll 1
    for (int ch = 0; ch < 9; ch++) {
        float* Wb = Wst + (ch & 1) * 3200;
        for (int li = tid; li < 32 * 24; li += 512) {
            int row = li / 24, kc = (li % 24) * 4;
            float4 v = *(const float4*)(w_qkv + (ch * 32 + row) * 96 + kc);
            v.x = tf32r(v.x); v.y = tf32r(v.y); v.z = tf32r(v.z); v.w = tf32r(v.w);
            *(float4*)&Wb[row * SA + kc] = v;
        }
        __syncthreads();
        float acc[2][4] = {{0.f,0.f,0.f,0.f},{0.f,0.f,0.f,0.f}};
        #pragma unroll
        for (int kk = 0; kk < 12; kk++) {
            #pragma unroll
            for (int ns = 0; ns < 2; ns++) {
                const float* Br = Wb + (wg * 16 + ns * 8 + g) * SA + kk * 8 + t4;
                mma8(acc[ns], af[kk][0], af[kk][1], af[kk][2], af[kk][3],
                     Br[0], Br[4]);
            }
        }
        int cb = (ch % 3) * 32 + wg * 16;
        int gb = (ch / 3) * 96 + cb;
        float* dst; int SD; float mul;
        if (ch < 3)      { dst = XW; SD = SA; mul = qscale; }
        else if (ch < 6) { dst = Kb; SD = SA; mul = 1.f; }
        else             { dst = Vb; SD = SV; mul = 1.f; }
        #pragma unroll
        for (int ns = 0; ns < 2; ns++) {
            int col = cb + ns * 8 + 2 * t4;
            float bx = b_qkv[gb + ns * 8 + 2 * t4];
            float by = b_qkv[gb + ns * 8 + 2 * t4 + 1];
            *(float2*)&dst[r0 * SD + col] =
                make_float2(tf32r((acc[ns][0] + bx) * mul), tf32r((acc[ns][1] + by) * mul));
            *(float2*)&dst[(r0 + 8) * SD + col] =
                make_float2(tf32r((acc[ns][2] + bx) * mul), tf32r((acc[ns][3] + by) * mul));
        }
    }
    __syncthreads();

    // ---- stage Wc (own region; covered by the attention-end barrier) ----
    for (int li = tid; li < 96 * 24; li += 512) {
        int row = li / 24, kc = (li % 24) * 4;
        *(float4*)&WcS[row * SA + kc] = *(const float4*)(g_wc + row * 96 + kc);
    }

    // ---- attention: head-parallel, zero barriers ----
    attn_head(XW, Kb, Vb, wg * 32, ws, g, t4);          // pass 0: heads 0,1
    if (wg == 0) attn_head(XW, Kb, Vb, 64, ws, g, t4);  // pass 1: head 2
    __syncthreads();

    // ---- combined out∘proj: final = O @ Wc^T + bc  (barrier-free) ----
    #pragma unroll
    for (int kk = 0; kk < 12; kk++) {
        const float* Ar = XW + r0 * SA + kk * 8 + t4;
        af[kk][0] = Ar[0];
        af[kk][1] = Ar[8 * SA];
        af[kk][2] = Ar[4];
        af[kk][3] = Ar[8 * SA + 4];
    }
    #pragma unroll 1
    for (int ch = 0; ch < 3; ch++) {
        float acc[2][4] = {{0.f,0.f,0.f,0.f},{0.f,0.f,0.f,0.f}};
        #pragma unroll
        for (int kk = 0; kk < 12; kk++) {
            #pragma unroll
            for (int ns = 0; ns < 2; ns++) {
                const float* Br = WcS + (ch * 32 + wg * 16 + ns * 8 + g) * SA + kk * 8 + t4;
                mma8(acc[ns], af[kk][0], af[kk][1], af[kk][2], af[kk][3],
                     Br[0], Br[4]);
            }
        }
        #pragma unroll
        for (int ns = 0; ns < 2; ns++) {
            int col = ch * 32 + wg * 16 + ns * 8 + 2 * t4;
            float bx = g_bc[col], by = g_bc[col + 1];
            *(float2*)&Kb[r0 * SA + col] =
                make_float2(acc[ns][0] + bx, acc[ns][1] + by);
            *(float2*)&Kb[(r0 + 8) * SA + col] =
                make_float2(acc[ns][2] + bx, acc[ns][3] + by);
        }
    }
    __syncthreads();

    // ---- scatter both windows (roll folded) ----
    for (int li = tid; li < 128 * 96; li += 512) {
        int r = li & 127, c = li >> 7;
        int w = w2 + (r >> 6);
        int t = r & 63;
        int b = w >> 10, wy = (w >> 5) & 31, wx = w & 31;
        int hh = ((wy << 3) + (t >> 3) + 4) & 255;
        int wc = ((wx << 3) + (t & 7) + 4) & 255;
        out[((b * 96 + c) << 16) + hh * 256 + wc] = Kb[r * SA + c];
    }
}

extern "C" void kernel_launch(void* const* d_in, const int* in_sizes, int n_in,
                              void* d_out, int out_size) {
    const float* x      = (const float*)d_in[0];
    const float* ln_g   = (const float*)d_in[1];
    const float* ln_b   = (const float*)d_in[2];
    const float* w_qkv  = (const float*)d_in[3];
    const float* b_qkv  = (const float*)d_in[4];
    const float* w_out  = (const float*)d_in[5];
    const float* b_out  = (const float*)d_in[6];
    const float* w_proj = (const float*)d_in[7];
    const float* b_proj = (const float*)d_in[8];
    float* out = (float*)d_out;

    combine_wb<<<96, 96>>>(w_out, b_out, w_proj, b_proj);
    cudaFuncSetAttribute(swin_mma7_kernel,
                         cudaFuncAttributeMaxDynamicSharedMemorySize, SMEM_BYTES);
    swin_mma7_kernel<<<4096, 512, SMEM_BYTES>>>(
        x, ln_g, ln_b, w_qkv, b_qkv, out);
}

// round 16
// speedup vs baseline: 3.4538x; 1.7923x over previous
#include <cuda_runtime.h>
#include <cuda_fp16.h>
#include <cstdint>

// Swin shifted-window attention, fused, fp16 mma.sync m16n8k16 (fp32 accum).
// 1 window/CTA, 8192 CTAs, 256 threads, 72KB smem, target 3 CTAs/SM.
// P->A-frag conversion is pure register packing (no shuffles). V stored
// transposed for contiguous half2 B-frags. Final result scattered from regs.

#define SA2  104   // XW/Kb/W row stride in halves (52 words -> conflict-free)
#define SVT  72    // VT row stride in halves

#define F_XW 0
#define F_K  3328
#define F_VT 6656
#define F_R  10112                 // Xf (fp32 gather) | later: Wst + WcS
#define F_WST F_R                  // 2 x 1664 floats (32x104 halves each)
#define F_WC  (F_R + 3328)         // 96x104 halves = 4992 floats
#define SMEM_FLOATS 18432
#define SMEM_BYTES  (SMEM_FLOATS * 4)

__device__ __align__(16) __half g_wq_h[288 * 96];  // fp16 w_qkv
__device__ __align__(16) __half g_wc_h[96 * 96];   // fp16 (w_proj @ w_out)
__device__ float g_bc[96];                         // w_proj @ b_out + b_proj

static __device__ __forceinline__ uint32_t h2u(float a, float b) {
    __half2 h = __floats2half2_rn(a, b);
    return *reinterpret_cast<uint32_t*>(&h);
}
static __device__ __forceinline__ void mma16(float* d, uint32_t a0, uint32_t a1,
                                             uint32_t a2, uint32_t a3,
                                             uint32_t b0, uint32_t b1) {
    asm volatile(
        "mma.sync.aligned.m16n8k16.row.col.f32.f16.f16.f32 "
        "{%0,%1,%2,%3}, {%4,%5,%6,%7}, {%8,%9}, {%0,%1,%2,%3};"
        : "+f"(d[0]), "+f"(d[1]), "+f"(d[2]), "+f"(d[3])
        : "r"(a0), "r"(a1), "r"(a2), "r"(a3), "r"(b0), "r"(b1));
}

__global__ void prep_wq(const float* __restrict__ w_qkv) {
    int i = blockIdx.x * 256 + threadIdx.x;
    if (i < 288 * 96) g_wq_h[i] = __float2half(w_qkv[i]);
}
__global__ void combine_wb(const float* __restrict__ w_out, const float* __restrict__ b_out,
                           const float* __restrict__ w_proj, const float* __restrict__ b_proj) {
    int row = blockIdx.x, col = threadIdx.x;
    float s = 0.f;
    #pragma unroll 4
    for (int k = 0; k < 96; k++) s += w_proj[row * 96 + k] * w_out[k * 96 + col];
    g_wc_h[row * 96 + col] = __float2half(s);
    if (col == 0) {
        float bs = b_proj[row];
        for (int k = 0; k < 96; k++) bs += w_proj[row * 96 + k] * b_out[k];
        g_bc[row] = bs;
    }
}

// One head, one 16-row strip. S = Q_h K_h^T, softmax in registers,
// O = P V_h written over Q_h cols of XW (own rows only, race-free).
static __device__ __forceinline__ void attn_head(__half* __restrict__ XWh,
                                                 const __half* __restrict__ Kbh,
                                                 const __half* __restrict__ VTh,
                                                 int ho, int ws, int g, int t4)
{
    const int sr = ws * 16 + g;
    float sacc[8][4];
    #pragma unroll
    for (int ns = 0; ns < 8; ns++)
        #pragma unroll
        for (int j = 0; j < 4; j++) sacc[ns][j] = 0.f;

    // S: 16x64, K=32 -> 2 k16-chunks
    #pragma unroll
    for (int kk = 0; kk < 2; kk++) {
        const __half* Ar = XWh + sr * SA2 + ho + kk * 16 + 2 * t4;
        uint32_t a0 = *(const uint32_t*)Ar;
        uint32_t a1 = *(const uint32_t*)(Ar + 8 * SA2);
        uint32_t a2 = *(const uint32_t*)(Ar + 8);
        uint32_t a3 = *(const uint32_t*)(Ar + 8 * SA2 + 8);
        #pragma unroll
        for (int ns = 0; ns < 8; ns++) {
            const __half* Br = Kbh + (ns * 8 + g) * SA2 + ho + kk * 16 + 2 * t4;
            mma16(sacc[ns], a0, a1, a2, a3,
                  *(const uint32_t*)Br, *(const uint32_t*)(Br + 8));
        }
    }
    // softmax rows sr (elems 0,1) and sr+8 (elems 2,3)
    float mxlo = -1e30f, mxhi = -1e30f;
    #pragma unroll
    for (int ns = 0; ns < 8; ns++) {
        mxlo = fmaxf(mxlo, fmaxf(sacc[ns][0], sacc[ns][1]));
        mxhi = fmaxf(mxhi, fmaxf(sacc[ns][2], sacc[ns][3]));
    }
    mxlo = fmaxf(mxlo, __shfl_xor_sync(0xffffffffu, mxlo, 1));
    mxlo = fmaxf(mxlo, __shfl_xor_sync(0xffffffffu, mxlo, 2));
    mxhi = fmaxf(mxhi, __shfl_xor_sync(0xffffffffu, mxhi, 1));
    mxhi = fmaxf(mxhi, __shfl_xor_sync(0xffffffffu, mxhi, 2));
    float slo = 0.f, shi = 0.f;
    #pragma unroll
    for (int ns = 0; ns < 8; ns++) {
        sacc[ns][0] = __expf(sacc[ns][0] - mxlo);
        sacc[ns][1] = __expf(sacc[ns][1] - mxlo);
        sacc[ns][2] = __expf(sacc[ns][2] - mxhi);
        sacc[ns][3] = __expf(sacc[ns][3] - mxhi);
        slo += sacc[ns][0] + sacc[ns][1];
        shi += sacc[ns][2] + sacc[ns][3];
    }
    slo += __shfl_xor_sync(0xffffffffu, slo, 1);
    slo += __shfl_xor_sync(0xffffffffu, slo, 2);
    shi += __shfl_xor_sync(0xffffffffu, shi, 1);
    shi += __shfl_xor_sync(0xffffffffu, shi, 2);
    float ilo = 1.f / slo, ihi = 1.f / shi;
    #pragma unroll
    for (int ns = 0; ns < 8; ns++) {
        sacc[ns][0] *= ilo; sacc[ns][1] *= ilo;
        sacc[ns][2] *= ihi; sacc[ns][3] *= ihi;
    }
    // O = P @ V_h : C-frag -> fp16 A-frag by packing (cols 2t4,2t4+1 match)
    float oacc[4][4];
    #pragma unroll
    for (int ns = 0; ns < 4; ns++)
        #pragma unroll
        for (int j = 0; j < 4; j++) oacc[ns][j] = 0.f;
    #pragma unroll
    for (int kk = 0; kk < 4; kk++) {
        uint32_t a0 = h2u(sacc[2*kk][0],   sacc[2*kk][1]);
        uint32_t a1 = h2u(sacc[2*kk][2],   sacc[2*kk][3]);
        uint32_t a2 = h2u(sacc[2*kk+1][0], sacc[2*kk+1][1]);
        uint32_t a3 = h2u(sacc[2*kk+1][2], sacc[2*kk+1][3]);
        #pragma unroll
        for (int ns = 0; ns < 4; ns++) {
            const __half* Br = VTh + (ho + ns * 8 + g) * SVT + kk * 16 + 2 * t4;
            mma16(oacc[ns], a0, a1, a2, a3,
                  *(const uint32_t*)Br, *(const uint32_t*)(Br + 8));
        }
    }
    #pragma unroll
    for (int ns = 0; ns < 4; ns++) {
        int col = ho + ns * 8 + 2 * t4;
        *(uint32_t*)&XWh[sr * SA2 + col]       = h2u(oacc[ns][0], oacc[ns][1]);
        *(uint32_t*)&XWh[(sr + 8) * SA2 + col] = h2u(oacc[ns][2], oacc[ns][3]);
    }
}

__global__ __launch_bounds__(256, 3)
void swin_fp16_kernel(const float* __restrict__ x,
                      const float* __restrict__ ln_g, const float* __restrict__ ln_b,
                      const float* __restrict__ b_qkv,
                      float* __restrict__ out)
{
    extern __shared__ float sm[];
    __half* XWh = (__half*)(sm + F_XW);   // y -> Q -> O (half)
    __half* Kbh = (__half*)(sm + F_K);    // K (half)
    __half* VTh = (__half*)(sm + F_VT);   // V transposed [96][SVT] (half)
    float*  Xf  = sm + F_R;               // fp32 gather buffer (dies after LN)
    __half* Wsth= (__half*)(sm + F_WST);  // qkv staging double buffer (half)
    __half* WcSh= (__half*)(sm + F_WC);   // combined weight [96][SA2] (half)

    const int tid  = threadIdx.x;
    const int wid  = tid >> 5;
    const int lane = tid & 31;
    const int g    = lane >> 2;
    const int t4   = lane & 3;
    const int ws   = wid & 3;   // M strip
    const int wg   = wid >> 2;  // N half / head group

    const int wb = blockIdx.x;
    const int b  = wb >> 10;
    const int wy = (wb >> 5) & 31, wx = wb & 31;

    // ---- gather (roll folded) into fp32 Xf ----
    for (int li = tid; li < 64 * 96; li += 256) {
        int tk = li & 63, c = li >> 6;
        int hh = ((wy << 3) + (tk >> 3) + 4) & 255;
        int wc = ((wx << 3) + (tk & 7) + 4) & 255;
        Xf[tk * 100 + c] = x[((b * 96 + c) << 16) + hh * 256 + wc];
    }
    __syncthreads();

    // ---- LayerNorm fp32 stats; write y as half into XWh ----
    {
        int tk = tid >> 2, s = tid & 3;
        const float* Xr = Xf + tk * 100 + s * 24;
        float sum = 0.f, sq = 0.f;
        float2 v[12];
        #pragma unroll
        for (int j = 0; j < 12; j++) {
            v[j] = *(const float2*)(Xr + 2 * j);
            sum += v[j].x + v[j].y;
            sq  += v[j].x * v[j].x + v[j].y * v[j].y;
        }
        sum += __shfl_xor_sync(0xffffffffu, sum, 1);
        sum += __shfl_xor_sync(0xffffffffu, sum, 2);
        sq  += __shfl_xor_sync(0xffffffffu, sq, 1);
        sq  += __shfl_xor_sync(0xffffffffu, sq, 2);
        float mu = sum * (1.f / 96.f);
        float rs = rsqrtf(sq * (1.f / 96.f) - mu * mu + 1e-5f);
        #pragma unroll
        for (int j = 0; j < 12; j++) {
            int c = s * 24 + 2 * j;
            float y0 = (v[j].x - mu) * rs * ln_g[c]     + ln_b[c];
            float y1 = (v[j].y - mu) * rs * ln_g[c + 1] + ln_b[c + 1];
            *(uint32_t*)&XWh[tk * SA2 + c] = h2u(y0, y1);
        }
    }
    __syncthreads();

    const float qscale = 0.17677669529663687f;  // 1/sqrt(32)
    const int   r0 = ws * 16 + g;

    // ---- snapshot fp16 A-fragments of y (6 k16-chunks) ----
    uint32_t af[6][4];
    #pragma unroll
    for (int kk = 0; kk < 6; kk++) {
        const __half* Ar = XWh + r0 * SA2 + kk * 16 + 2 * t4;
        af[kk][0] = *(const uint32_t*)Ar;
        af[kk][1] = *(const uint32_t*)(Ar + 8 * SA2);
        af[kk][2] = *(const uint32_t*)(Ar + 8);
        af[kk][3] = *(const uint32_t*)(Ar + 8 * SA2 + 8);
    }
    __syncthreads();   // frags held; XWh may be overwritten by Q

    // ---- QKV: 9 chunks of 32 features; double-buffered half staging ----
    #pragma unroll 1
    for (int ch = 0; ch < 9; ch++) {
        __half* Wb = Wsth + (ch & 1) * 3328;
        for (int li = tid; li < 384; li += 256) {
            int row = li / 12, k8 = (li % 12) * 8;
            *(uint4*)&Wb[row * SA2 + k8] =
                *(const uint4*)(g_wq_h + (ch * 32 + row) * 96 + k8);
        }
        __syncthreads();
        float acc[2][4] = {{0.f,0.f,0.f,0.f},{0.f,0.f,0.f,0.f}};
        #pragma unroll
        for (int kk = 0; kk < 6; kk++) {
            #pragma unroll
            for (int ns = 0; ns < 2; ns++) {
                const __half* Br = Wb + (wg * 16 + ns * 8 + g) * SA2 + kk * 16 + 2 * t4;
                mma16(acc[ns], af[kk][0], af[kk][1], af[kk][2], af[kk][3],
                      *(const uint32_t*)Br, *(const uint32_t*)(Br + 8));
            }
        }
        int cb = (ch % 3) * 32 + wg * 16;
        int gb = (ch / 3) * 96 + cb;
        #pragma unroll
        for (int ns = 0; ns < 2; ns++) {
            int col = cb + ns * 8 + 2 * t4;
            float bx = b_qkv[gb + ns * 8 + 2 * t4];
            float by = b_qkv[gb + ns * 8 + 2 * t4 + 1];
            float v0 = acc[ns][0] + bx, v1 = acc[ns][1] + by;
            float v2 = acc[ns][2] + bx, v3 = acc[ns][3] + by;
            if (ch < 3) {
                v0 *= qscale; v1 *= qscale; v2 *= qscale; v3 *= qscale;
                *(uint32_t*)&XWh[r0 * SA2 + col]       = h2u(v0, v1);
                *(uint32_t*)&XWh[(r0 + 8) * SA2 + col] = h2u(v2, v3);
            } else if (ch < 6) {
                *(uint32_t*)&Kbh[r0 * SA2 + col]       = h2u(v0, v1);
                *(uint32_t*)&Kbh[(r0 + 8) * SA2 + col] = h2u(v2, v3);
            } else {
                VTh[col * SVT + r0]           = __float2half(v0);
                VTh[(col + 1) * SVT + r0]     = __float2half(v1);
                VTh[col * SVT + r0 + 8]       = __float2half(v2);
                VTh[(col + 1) * SVT + r0 + 8] = __float2half(v3);
            }
        }
        __syncthreads();
    }

    // ---- stage Wc (covered by attention-end barrier) ----
    for (int li = tid; li < 1152; li += 256) {
        int row = li / 12, k8 = (li % 12) * 8;
        *(uint4*)&WcSh[row * SA2 + k8] = *(const uint4*)(g_wc_h + row * 96 + k8);
    }

    // ---- attention: head-parallel, zero barriers ----
    attn_head(XWh, Kbh, VTh, wg * 32, ws, g, t4);          // heads 0,1
    if (wg == 0) attn_head(XWh, Kbh, VTh, 64, ws, g, t4);  // head 2
    __syncthreads();

    // ---- combined out∘proj: final = O @ Wc^T + bc, kept in registers ----
    #pragma unroll
    for (int kk = 0; kk < 6; kk++) {
        const __half* Ar = XWh + r0 * SA2 + kk * 16 + 2 * t4;
        af[kk][0] = *(const uint32_t*)Ar;
        af[kk][1] = *(const uint32_t*)(Ar + 8 * SA2);
        af[kk][2] = *(const uint32_t*)(Ar + 8);
        af[kk][3] = *(const uint32_t*)(Ar + 8 * SA2 + 8);
    }
    float facc[3][2][4];
    #pragma unroll
    for (int ch = 0; ch < 3; ch++)
        #pragma unroll
        for (int ns = 0; ns < 2; ns++)
            #pragma unroll
            for (int j = 0; j < 4; j++) facc[ch][ns][j] = 0.f;
    #pragma unroll
    for (int ch = 0; ch < 3; ch++)
        #pragma unroll
        for (int kk = 0; kk < 6; kk++)
            #pragma unroll
            for (int ns = 0; ns < 2; ns++) {
                const __half* Br = WcSh + (ch * 32 + wg * 16 + ns * 8 + g) * SA2 + kk * 16 + 2 * t4;
                mma16(facc[ch][ns], af[kk][0], af[kk][1], af[kk][2], af[kk][3],
                      *(const uint32_t*)Br, *(const uint32_t*)(Br + 8));
            }

    // ---- scatter directly from registers (fp32, roll folded) ----
    {
        int tlo = r0, thi = r0 + 8;
        int hhlo = ((wy << 3) + (tlo >> 3) + 4) & 255;
        int wclo = ((wx << 3) + (tlo & 7) + 4) & 255;
        int hhhi = ((wy << 3) + (thi >> 3) + 4) & 255;
        int wchi = ((wx << 3) + (thi & 7) + 4) & 255;
        int offlo = hhlo * 256 + wclo;
        int offhi = hhhi * 256 + wchi;
        int cbase = b * 96;
        #pragma unroll
        for (int ch = 0; ch < 3; ch++)
            #pragma unroll
            for (int ns = 0; ns < 2; ns++) {
                int c0 = ch * 32 + wg * 16 + ns * 8 + 2 * t4;
                float b0 = g_bc[c0], b1 = g_bc[c0 + 1];
                out[((cbase + c0    ) << 16) + offlo] = facc[ch][ns][0] + b0;
                out[((cbase + c0 + 1) << 16) + offlo] = facc[ch][ns][1] + b1;
                out[((cbase + c0    ) << 16) + offhi] = facc[ch][ns][2] + b0;
                out[((cbase + c0 + 1) << 16) + offhi] = facc[ch][ns][3] + b1;
            }
    }
}

extern "C" void kernel_launch(void* const* d_in, const int* in_sizes, int n_in,
                              void* d_out, int out_size) {
    const float* x      = (const float*)d_in[0];
    const float* ln_g   = (const float*)d_in[1];
    const float* ln_b   = (const float*)d_in[2];
    const float* w_qkv  = (const float*)d_in[3];
    const float* b_qkv  = (const float*)d_in[4];
    const float* w_out  = (const float*)d_in[5];
    const float* b_out  = (const float*)d_in[6];
    const float* w_proj = (const float*)d_in[7];
    const float* b_proj = (const float*)d_in[8];
    float* out = (float*)d_out;

    prep_wq<<<108, 256>>>(w_qkv);
    combine_wb<<<96, 96>>>(w_out, b_out, w_proj, b_proj);
    cudaFuncSetAttribute(swin_fp16_kernel,
                         cudaFuncAttributeMaxDynamicSharedMemorySize, SMEM_BYTES);
    swin_fp16_kernel<<<8192, 256, SMEM_BYTES>>>(
        x, ln_g, ln_b, b_qkv, out);
}